// round 7
// baseline (speedup 1.0000x reference)
#include <cuda_runtime.h>
#include <cstdint>

#define Bn 128
#define Ln 1024
#define Hn 1024
#define Tn 9
#define NEG_INF (-3.0e38f)

#define NTHREADS 512
#define NWARPS 16

typedef unsigned long long u64;

// ---- f32x2 packed-FMA helpers (sm_103a FFMA2; only reachable via PTX) ----
__device__ __forceinline__ u64 ffma2(u64 a, u64 b, u64 c) {
    u64 d;
    asm("fma.rn.f32x2 %0, %1, %2, %3;" : "=l"(d) : "l"(a), "l"(b), "l"(c));
    return d;
}
__device__ __forceinline__ void upk(u64 v, float& lo, float& hi) {
    asm("mov.b64 {%0, %1}, %2;" : "=f"(lo), "=f"(hi) : "l"(v));
}

// dynamic smem layout: se[Ln*12+64] | part[16*32*40] | hist8[Ln*16]
#define SE_F (Ln * 12 + 64)
#define PART_F (NWARPS * 32 * 40)
#define HIST_B (Ln * 16)
#define DYN_BYTES (SE_F * 4 + PART_F * 4 + HIST_B)

// ---------------------------------------------------------------------------
// Fused kernel: one block per batch, 16 warps.
//   Phase A: 16 warps, 4 rows/warp/tile, f32x2 FMA, transpose-reduce.
//            Latency hidden by warp count (4 warps/SMSP), no double buffer.
//   Phase B: warp 0 slim Viterbi forward; score vectors overwrite emissions.
//   Phase C: 512 threads compute backpointers in parallel (bit-identical).
//   Phase D: backtrace + coalesced writeout.
// ---------------------------------------------------------------------------
__global__ __launch_bounds__(NTHREADS, 1) void fused_kernel(
    const float* __restrict__ x, const void* __restrict__ mask_raw,
    const float* __restrict__ W, const float* __restrict__ bias,
    const float* __restrict__ startT, const float* __restrict__ endT,
    const float* __restrict__ trans, float* __restrict__ out)
{
    extern __shared__ __align__(16) float dyn[];
    float* se = dyn;                                 // [Ln][12] emissions/scores
    float* part = dyn + SE_F;                        // [16][32][40] reduce scratch
    uint8_t* hist8 = (uint8_t*)(part + PART_F);      // [Ln][16] backpointers

    __shared__ float ttr[Tn * Tn];
    __shared__ uint8_t tags[Ln];
    __shared__ int s_len, s_lasttag;
    __shared__ float s_best;

    const int b = blockIdx.x;
    const int warp = threadIdx.x >> 5;
    const int lane = threadIdx.x & 31;

    if (threadIdx.x < Tn * Tn) ttr[threadIdx.x] = trans[threadIdx.x];

    // =============================== Phase A: emit ===========================
    // E[l][t] = dot(x[b,l,:], W[t,:]) + bias[t] -> se[l*12 + t]
    const float bias_a = bias[lane % Tn];
    const float bias_b = bias[(lane + 32) % Tn];    // lanes < 4
    const int dst_a = (lane / 9) * 12 + (lane % 9); // s -> (s/9)*12 + s%9
    const int dst_b = ((lane + 32) / 9) * 12 + ((lane + 32) % 9);

    const ulonglong2* X = (const ulonglong2*)(x + (size_t)b * Ln * Hn);
    float* pw = part + (warp * 32 + lane) * 40;
    const float* pb = part + warp * 32 * 40;

    for (int tl = 0; tl < 16; tl++) {
        const int row0 = (tl * NWARPS + warp) * 4;

        u64 acc[4][Tn];
#pragma unroll
        for (int r = 0; r < 4; r++)
#pragma unroll
            for (int t = 0; t < Tn; t++) acc[r][t] = 0ull;

#pragma unroll 2
        for (int c = 0; c < 8; c++) {
            ulonglong2 va[4];
#pragma unroll
            for (int r = 0; r < 4; r++)
                va[r] = __ldcs(X + (row0 + r) * 256 + lane + 32 * c);
            const int k = (lane + 32 * c) * 4;
#pragma unroll
            for (int t = 0; t < Tn; t++) {
                const ulonglong2 w = *(const ulonglong2*)(W + t * Hn + k);
#pragma unroll
                for (int r = 0; r < 4; r++) {
                    acc[r][t] = ffma2(va[r].x, w.x, acc[r][t]);
                    acc[r][t] = ffma2(va[r].y, w.y, acc[r][t]);
                }
            }
        }

        // pair-sum packed halves -> 36 per-lane partials
#pragma unroll
        for (int r = 0; r < 4; r++)
#pragma unroll
            for (int t = 0; t < Tn; t++) {
                float lo, hi;
                upk(acc[r][t], lo, hi);
                pw[r * Tn + t] = lo + hi;
            }
        __syncwarp();

        // transpose reduce: lane s sums column s (s = r*9+t) over 32 lanes
        {
            float a0 = 0.f, a1 = 0.f, a2 = 0.f, a3 = 0.f;
#pragma unroll
            for (int L = 0; L < 32; L += 4) {
                a0 += pb[(L + 0) * 40 + lane];
                a1 += pb[(L + 1) * 40 + lane];
                a2 += pb[(L + 2) * 40 + lane];
                a3 += pb[(L + 3) * 40 + lane];
            }
            se[row0 * 12 + dst_a] = (a0 + a1) + (a2 + a3) + bias_a;
        }
        if (lane < 4) {
            const int s = lane + 32;
            float a0 = 0.f, a1 = 0.f, a2 = 0.f, a3 = 0.f;
#pragma unroll
            for (int L = 0; L < 32; L += 4) {
                a0 += pb[(L + 0) * 40 + s];
                a1 += pb[(L + 1) * 40 + s];
                a2 += pb[(L + 2) * 40 + s];
                a3 += pb[(L + 3) * 40 + s];
            }
            se[row0 * 12 + dst_b] = (a0 + a1) + (a2 + a3) + bias_b;
        }
        __syncwarp();
    }
    __syncthreads();

    // ======================= Phase B: forward (warp 0) =======================
    if (warp == 0) {
        const int j = lane;

        // mask dtype detection + length (prefix mask)
        const unsigned* mw = (const unsigned*)mask_raw;
        const unsigned first = mw[0];
        const bool word_mask = (first == 1u) || (first == 0x3F800000u);
        int len = 0;
        if (word_mask) {
            const unsigned* m = mw + (size_t)b * Ln;
            for (int k = lane; k < Ln; k += 32) len += (m[k] != 0u);
        } else {
            const uint8_t* m = (const uint8_t*)mask_raw + (size_t)b * Ln;
            for (int k = lane; k < Ln; k += 32) len += (m[k] != 0);
        }
#pragma unroll
        for (int o = 16; o; o >>= 1) len += __shfl_xor_sync(0xffffffffu, len, o);

        const int jc = (j < Tn) ? j : 8;
        const int hidx = (j < 11) ? j : 11;  // lanes >= 9 -> pad cols 9..11
        float tcol[Tn];
#pragma unroll
        for (int i = 0; i < Tn; i++) tcol[i] = ttr[i * Tn + jc];

        float score = (j < Tn) ? startT[j] + se[j] : NEG_INF;

        const float* erow = se + 12;  // emission row l (starts at l=1)
        float* srow = se;             // score-vector row l-1

        for (int l = 1; l < len; l++) {
            srow[hidx] = score;  // store sv_{l-1} over consumed emission row
            asm volatile("" ::: "memory");
            const float4 sa = *(const float4*)(srow);
            const float4 sb = *(const float4*)(srow + 4);
            const float s8v = srow[8];
            const float e = erow[j];

            const float cv0 = sa.x + tcol[0];
            const float cv1 = sa.y + tcol[1];
            const float cv2 = sa.z + tcol[2];
            const float cv3 = sa.w + tcol[3];
            const float cv4 = sb.x + tcol[4];
            const float cv5 = sb.y + tcol[5];
            const float cv6 = sb.z + tcol[6];
            const float cv7 = sb.w + tcol[7];
            const float cv8 = s8v + tcol[8];

            const float m0 = fmaxf(cv0, cv1);
            const float m1 = fmaxf(cv2, cv3);
            const float m2 = fmaxf(cv4, cv5);
            const float m3 = fmaxf(cv6, cv7);
            const float best = fmaxf(fmaxf(fmaxf(m0, m1), fmaxf(m2, m3)), cv8);

            score = best + e;
            srow += 12;
            erow += 12;
        }

        // final scores + argmax over states (exchange via row len-1)
        const float fin = (j < Tn) ? score + endT[j] : NEG_INF;
        srow[hidx] = fin;
        asm volatile("" ::: "memory");
        const float4 fa = *(const float4*)(srow);
        const float4 fb = *(const float4*)(srow + 4);
        const float f8v = srow[8];
        const float f0 = fmaxf(fa.x, fa.y);
        const float f1 = fmaxf(fa.z, fa.w);
        const float f2 = fmaxf(fb.x, fb.y);
        const float f3 = fmaxf(fb.z, fb.w);
        const float best_f = fmaxf(fmaxf(fmaxf(f0, f1), fmaxf(f2, f3)), f8v);
        const int g0 = (fa.x == best_f) ? 0 : 9;
        const int g1 = (fa.y == best_f) ? 1 : 9;
        const int g2 = (fa.z == best_f) ? 2 : 9;
        const int g3 = (fa.w == best_f) ? 3 : 9;
        const int g4 = (fb.x == best_f) ? 4 : 9;
        const int g5 = (fb.y == best_f) ? 5 : 9;
        const int g6 = (fb.z == best_f) ? 6 : 9;
        const int g7 = (fb.w == best_f) ? 7 : 9;
        const int g8 = (f8v == best_f) ? 8 : 9;
        const int h0 = min(min(g0, g1), min(g2, g3));
        const int h1 = min(min(g4, g5), min(g6, g7));
        if (lane == 0) {
            s_len = len;
            s_best = best_f;
            s_lasttag = min(min(h0, h1), g8);
        }
    }
    __syncthreads();

    // ================= Phase C: parallel backpointers (all threads) ==========
    const int len = s_len;
    for (int l = 1 + (int)threadIdx.x; l < len; l += NTHREADS) {
        const float* sv = se + (l - 1) * 12;
        const float p0 = sv[0], p1 = sv[1], p2 = sv[2], p3 = sv[3], p4 = sv[4];
        const float p5 = sv[5], p6 = sv[6], p7 = sv[7], p8 = sv[8];
#pragma unroll
        for (int j = 0; j < Tn; j++) {
            const float cv0 = p0 + ttr[0 * Tn + j];
            const float cv1 = p1 + ttr[1 * Tn + j];
            const float cv2 = p2 + ttr[2 * Tn + j];
            const float cv3 = p3 + ttr[3 * Tn + j];
            const float cv4 = p4 + ttr[4 * Tn + j];
            const float cv5 = p5 + ttr[5 * Tn + j];
            const float cv6 = p6 + ttr[6 * Tn + j];
            const float cv7 = p7 + ttr[7 * Tn + j];
            const float cv8 = p8 + ttr[8 * Tn + j];
            const float m0 = fmaxf(cv0, cv1);
            const float m1 = fmaxf(cv2, cv3);
            const float m2 = fmaxf(cv4, cv5);
            const float m3 = fmaxf(cv6, cv7);
            const float best = fmaxf(fmaxf(fmaxf(m0, m1), fmaxf(m2, m3)), cv8);
            const int e0 = (cv0 == best) ? 0 : 9;
            const int e1 = (cv1 == best) ? 1 : 9;
            const int e2 = (cv2 == best) ? 2 : 9;
            const int e3 = (cv3 == best) ? 3 : 9;
            const int e4 = (cv4 == best) ? 4 : 9;
            const int e5 = (cv5 == best) ? 5 : 9;
            const int e6 = (cv6 == best) ? 6 : 9;
            const int e7 = (cv7 == best) ? 7 : 9;
            const int e8 = (cv8 == best) ? 8 : 9;
            const int a0 = min(min(e0, e1), min(e2, e3));
            const int a1 = min(min(e4, e5), min(e6, e7));
            hist8[l * 16 + j] = (uint8_t)min(min(a0, a1), e8);
        }
    }
    __syncthreads();

    // ===================== Phase D: backtrace (thread 0) =====================
    if (threadIdx.x == 0) {
        int tag = s_lasttag;
        tags[len - 1] = (uint8_t)tag;
        for (int l = len - 2; l >= 0; --l) {
            tag = (int)hist8[(l + 1) * 16 + tag];
            tags[l] = (uint8_t)tag;
        }
    }
    __syncthreads();

    // =============================== write out ===============================
    float* ot = out + (size_t)b * Ln;
    for (int k = threadIdx.x; k < Ln; k += NTHREADS)
        ot[k] = (k < len) ? (float)tags[k] : 0.f;
    if (threadIdx.x == 0) out[(size_t)Bn * Ln + b] = s_best;
}

// ---------------------------------------------------------------------------
extern "C" void kernel_launch(void* const* d_in, const int* in_sizes, int n_in,
                              void* d_out, int out_size)
{
    const float* x    = (const float*)d_in[0];  // encoder_output [B,L,H2]
    const void*  mask = d_in[1];                // mask [B,L]
    const float* W    = (const float*)d_in[2];  // [T,H2]
    const float* bias = (const float*)d_in[3];  // [T]
    const float* st   = (const float*)d_in[4];  // start_transitions [T]
    const float* en   = (const float*)d_in[5];  // end_transitions [T]
    const float* tr   = (const float*)d_in[6];  // transitions [T,T]
    float* out = (float*)d_out;                 // tags [B*L] then best_score [B]

    cudaFuncSetAttribute(fused_kernel,
                         cudaFuncAttributeMaxDynamicSharedMemorySize, DYN_BYTES);
    fused_kernel<<<Bn, NTHREADS, DYN_BYTES>>>(x, mask, W, bias, st, en, tr, out);
}

// round 8
// speedup vs baseline: 1.3935x; 1.3935x over previous
#include <cuda_runtime.h>
#include <cstdint>

#define Bn 128
#define Ln 1024
#define Hn 1024
#define Tn 9
#define NEG_INF (-3.0e38f)

#define NTHREADS 288   // 8 emit warps + 1 viterbi consumer warp

typedef unsigned long long u64;

// ---- f32x2 packed-FMA helpers (sm_103a FFMA2; only reachable via PTX) ----
__device__ __forceinline__ u64 ffma2(u64 a, u64 b, u64 c) {
    u64 d;
    asm("fma.rn.f32x2 %0, %1, %2, %3;" : "=l"(d) : "l"(a), "l"(b), "l"(c));
    return d;
}
__device__ __forceinline__ void upk(u64 v, float& lo, float& hi) {
    asm("mov.b64 {%0, %1}, %2;" : "=f"(lo), "=f"(hi) : "l"(v));
}

// dynamic smem layout: se[Ln*12+64] | part[8*32*40] | hist8[Ln*16]
#define SE_F (Ln * 12 + 64)
#define PART_F (8 * 32 * 40)
#define HIST_B (Ln * 16)
#define DYN_BYTES (SE_F * 4 + PART_F * 4 + HIST_B)

// ---------------------------------------------------------------------------
// Fused kernel, one block per batch, 9 warps:
//   warps 0-7: emit (round-5 double-buffered f32x2 GEMM, unchanged),
//              publishing 32-row chunks via smem ready-counters.
//   warp 8:    Viterbi forward runs CONCURRENTLY, consuming chunks as they
//              become ready (spin on volatile counter + threadfence acquire).
//   then: parallel backpointers (288 thr), serial backtrace, writeout.
// ---------------------------------------------------------------------------
__global__ __launch_bounds__(NTHREADS, 1) void fused_kernel(
    const float* __restrict__ x, const void* __restrict__ mask_raw,
    const float* __restrict__ W, const float* __restrict__ bias,
    const float* __restrict__ startT, const float* __restrict__ endT,
    const float* __restrict__ trans, float* __restrict__ out)
{
    extern __shared__ __align__(16) float dyn[];
    float* se = dyn;                                 // [Ln][12] emissions/scores
    float* part = dyn + SE_F;                        // [8][32][40] reduce scratch
    uint8_t* hist8 = (uint8_t*)(part + PART_F);      // [Ln][16] backpointers

    __shared__ float ttr[Tn * Tn];
    __shared__ uint8_t tags[Ln];
    __shared__ int cnt[32];                          // per-chunk ready counters
    __shared__ int s_len, s_lasttag;
    __shared__ float s_best;

    const int b = blockIdx.x;
    const int warp = threadIdx.x >> 5;
    const int lane = threadIdx.x & 31;

    if (threadIdx.x < Tn * Tn) ttr[threadIdx.x] = trans[threadIdx.x];
    if (threadIdx.x < 32) cnt[threadIdx.x] = 0;
    __syncthreads();

    if (warp < 8) {
        // ============================ emit (producers) =======================
        const float bias_a = bias[lane % Tn];
        const float bias_b = bias[(lane + 32) % Tn];    // lanes < 4
        const int dst_a = (lane / 9) * 12 + (lane % 9); // s -> (s/9)*12 + s%9
        const int dst_b = ((lane + 32) / 9) * 12 + ((lane + 32) % 9);

        const ulonglong2* X = (const ulonglong2*)(x + (size_t)b * Ln * Hn);
        float* pw = part + (warp * 32 + lane) * 40;
        const float* pb = part + warp * 32 * 40;

        ulonglong2 va[4], vb[4];
        {   // preload tile 0, chunk 0
            const int row0 = warp * 4;
#pragma unroll
            for (int r = 0; r < 4; r++) va[r] = __ldcs(X + (row0 + r) * 256 + lane);
        }

        for (int g = 0; g < 32; g++) {
            const int row0 = g * 32 + warp * 4;
            const int row0n = (g < 31) ? row0 + 32 : row0;  // next tile (clamped)

            u64 acc[4][Tn];
#pragma unroll
            for (int r = 0; r < 4; r++)
#pragma unroll
                for (int t = 0; t < Tn; t++) acc[r][t] = 0ull;

#pragma unroll
            for (int c = 0; c < 8; c += 2) {
                // prefetch chunk c+1 into vb, compute va (chunk c)
#pragma unroll
                for (int r = 0; r < 4; r++)
                    vb[r] = __ldcs(X + (row0 + r) * 256 + lane + 32 * (c + 1));
                {
                    const int k = (lane + 32 * c) * 4;
#pragma unroll
                    for (int t = 0; t < Tn; t++) {
                        const ulonglong2 w = *(const ulonglong2*)(W + t * Hn + k);
#pragma unroll
                        for (int r = 0; r < 4; r++) {
                            acc[r][t] = ffma2(va[r].x, w.x, acc[r][t]);
                            acc[r][t] = ffma2(va[r].y, w.y, acc[r][t]);
                        }
                    }
                }
                // prefetch chunk c+2 (or next tile chunk 0) into va, compute vb
                const int cn = (c + 2 < 8) ? (c + 2) : 0;
                const int rown = (c + 2 < 8) ? row0 : row0n;
#pragma unroll
                for (int r = 0; r < 4; r++)
                    va[r] = __ldcs(X + (rown + r) * 256 + lane + 32 * cn);
                {
                    const int k = (lane + 32 * (c + 1)) * 4;
#pragma unroll
                    for (int t = 0; t < Tn; t++) {
                        const ulonglong2 w = *(const ulonglong2*)(W + t * Hn + k);
#pragma unroll
                        for (int r = 0; r < 4; r++) {
                            acc[r][t] = ffma2(vb[r].x, w.x, acc[r][t]);
                            acc[r][t] = ffma2(vb[r].y, w.y, acc[r][t]);
                        }
                    }
                }
            }

            // pair-sum packed halves -> 36 per-lane partials
#pragma unroll
            for (int r = 0; r < 4; r++)
#pragma unroll
                for (int t = 0; t < Tn; t++) {
                    float lo, hi;
                    upk(acc[r][t], lo, hi);
                    pw[r * Tn + t] = lo + hi;
                }
            __syncwarp();

            // transpose reduce: lane s sums column s (s = r*9+t) over 32 lanes
            {
                float a0 = 0.f, a1 = 0.f, a2 = 0.f, a3 = 0.f;
#pragma unroll
                for (int L = 0; L < 32; L += 4) {
                    a0 += pb[(L + 0) * 40 + lane];
                    a1 += pb[(L + 1) * 40 + lane];
                    a2 += pb[(L + 2) * 40 + lane];
                    a3 += pb[(L + 3) * 40 + lane];
                }
                se[row0 * 12 + dst_a] = (a0 + a1) + (a2 + a3) + bias_a;
            }
            if (lane < 4) {
                const int s = lane + 32;
                float a0 = 0.f, a1 = 0.f, a2 = 0.f, a3 = 0.f;
#pragma unroll
                for (int L = 0; L < 32; L += 4) {
                    a0 += pb[(L + 0) * 40 + s];
                    a1 += pb[(L + 1) * 40 + s];
                    a2 += pb[(L + 2) * 40 + s];
                    a3 += pb[(L + 3) * 40 + s];
                }
                se[row0 * 12 + dst_b] = (a0 + a1) + (a2 + a3) + bias_b;
            }
            __syncwarp();

            // publish chunk g (release: fence then count)
            if (lane == 0) {
                __threadfence_block();
                atomicAdd(&cnt[g], 1);
            }
        }
    } else {
        // ===================== Viterbi forward (consumer) ====================
        const int j = lane;

        // mask dtype detection + length (prefix mask) — independent of emit
        const unsigned* mw = (const unsigned*)mask_raw;
        const unsigned first = mw[0];
        const bool word_mask = (first == 1u) || (first == 0x3F800000u);
        int len = 0;
        if (word_mask) {
            const unsigned* m = mw + (size_t)b * Ln;
            for (int k = lane; k < Ln; k += 32) len += (m[k] != 0u);
        } else {
            const uint8_t* m = (const uint8_t*)mask_raw + (size_t)b * Ln;
            for (int k = lane; k < Ln; k += 32) len += (m[k] != 0);
        }
#pragma unroll
        for (int o = 16; o; o >>= 1) len += __shfl_xor_sync(0xffffffffu, len, o);

        const int jc = (j < Tn) ? j : 8;
        const int hidx = (j < 11) ? j : 11;  // lanes >= 9 -> pad cols 9..11
        float tcol[Tn];
#pragma unroll
        for (int i = 0; i < Tn; i++) tcol[i] = ttr[i * Tn + jc];
        const float stj = (j < Tn) ? startT[j] : 0.f;

        // wait for chunk 0 (acquire)
        while (*(volatile int*)&cnt[0] < 8) { }
        __threadfence_block();

        float score = (j < Tn) ? stj + se[j] : NEG_INF;

        const float* erow = se + 12;  // emission row l (starts at l=1)
        float* srow = se;             // score-vector row l-1

        for (int l = 1; l < len; l++) {
            if ((l & 31) == 0) {      // entering chunk l>>5: wait until ready
                while (*(volatile int*)&cnt[l >> 5] < 8) { }
                __threadfence_block();
            }
            srow[hidx] = score;  // store sv_{l-1} over consumed emission row
            asm volatile("" ::: "memory");
            const float4 sa = *(const float4*)(srow);
            const float4 sb = *(const float4*)(srow + 4);
            const float s8v = srow[8];
            const float e = erow[j];

            const float cv0 = sa.x + tcol[0];
            const float cv1 = sa.y + tcol[1];
            const float cv2 = sa.z + tcol[2];
            const float cv3 = sa.w + tcol[3];
            const float cv4 = sb.x + tcol[4];
            const float cv5 = sb.y + tcol[5];
            const float cv6 = sb.z + tcol[6];
            const float cv7 = sb.w + tcol[7];
            const float cv8 = s8v + tcol[8];

            const float m0 = fmaxf(cv0, cv1);
            const float m1 = fmaxf(cv2, cv3);
            const float m2 = fmaxf(cv4, cv5);
            const float m3 = fmaxf(cv6, cv7);
            const float best = fmaxf(fmaxf(fmaxf(m0, m1), fmaxf(m2, m3)), cv8);

            score = best + e;
            srow += 12;
            erow += 12;
        }

        // final scores + argmax over states (exchange via row len-1)
        const float fin = (j < Tn) ? score + endT[j] : NEG_INF;
        srow[hidx] = fin;
        asm volatile("" ::: "memory");
        const float4 fa = *(const float4*)(srow);
        const float4 fb = *(const float4*)(srow + 4);
        const float f8v = srow[8];
        const float f0 = fmaxf(fa.x, fa.y);
        const float f1 = fmaxf(fa.z, fa.w);
        const float f2 = fmaxf(fb.x, fb.y);
        const float f3 = fmaxf(fb.z, fb.w);
        const float best_f = fmaxf(fmaxf(fmaxf(f0, f1), fmaxf(f2, f3)), f8v);
        const int g0 = (fa.x == best_f) ? 0 : 9;
        const int g1 = (fa.y == best_f) ? 1 : 9;
        const int g2 = (fa.z == best_f) ? 2 : 9;
        const int g3 = (fa.w == best_f) ? 3 : 9;
        const int g4 = (fb.x == best_f) ? 4 : 9;
        const int g5 = (fb.y == best_f) ? 5 : 9;
        const int g6 = (fb.z == best_f) ? 6 : 9;
        const int g7 = (fb.w == best_f) ? 7 : 9;
        const int g8 = (f8v == best_f) ? 8 : 9;
        const int h0 = min(min(g0, g1), min(g2, g3));
        const int h1 = min(min(g4, g5), min(g6, g7));
        if (lane == 0) {
            s_len = len;
            s_best = best_f;
            s_lasttag = min(min(h0, h1), g8);
        }
    }
    __syncthreads();

    // ================= parallel backpointers (all 288 threads) ===============
    const int len = s_len;
    for (int l = 1 + (int)threadIdx.x; l < len; l += NTHREADS) {
        const float* sv = se + (l - 1) * 12;
        const float p0 = sv[0], p1 = sv[1], p2 = sv[2], p3 = sv[3], p4 = sv[4];
        const float p5 = sv[5], p6 = sv[6], p7 = sv[7], p8 = sv[8];
#pragma unroll
        for (int j = 0; j < Tn; j++) {
            const float cv0 = p0 + ttr[0 * Tn + j];
            const float cv1 = p1 + ttr[1 * Tn + j];
            const float cv2 = p2 + ttr[2 * Tn + j];
            const float cv3 = p3 + ttr[3 * Tn + j];
            const float cv4 = p4 + ttr[4 * Tn + j];
            const float cv5 = p5 + ttr[5 * Tn + j];
            const float cv6 = p6 + ttr[6 * Tn + j];
            const float cv7 = p7 + ttr[7 * Tn + j];
            const float cv8 = p8 + ttr[8 * Tn + j];
            const float m0 = fmaxf(cv0, cv1);
            const float m1 = fmaxf(cv2, cv3);
            const float m2 = fmaxf(cv4, cv5);
            const float m3 = fmaxf(cv6, cv7);
            const float best = fmaxf(fmaxf(fmaxf(m0, m1), fmaxf(m2, m3)), cv8);
            const int e0 = (cv0 == best) ? 0 : 9;
            const int e1 = (cv1 == best) ? 1 : 9;
            const int e2 = (cv2 == best) ? 2 : 9;
            const int e3 = (cv3 == best) ? 3 : 9;
            const int e4 = (cv4 == best) ? 4 : 9;
            const int e5 = (cv5 == best) ? 5 : 9;
            const int e6 = (cv6 == best) ? 6 : 9;
            const int e7 = (cv7 == best) ? 7 : 9;
            const int e8 = (cv8 == best) ? 8 : 9;
            const int a0 = min(min(e0, e1), min(e2, e3));
            const int a1 = min(min(e4, e5), min(e6, e7));
            hist8[l * 16 + j] = (uint8_t)min(min(a0, a1), e8);
        }
    }
    __syncthreads();

    // ======================= backtrace (thread 0) ============================
    if (threadIdx.x == 0) {
        int tag = s_lasttag;
        tags[len - 1] = (uint8_t)tag;
        for (int l = len - 2; l >= 0; --l) {
            tag = (int)hist8[(l + 1) * 16 + tag];
            tags[l] = (uint8_t)tag;
        }
    }
    __syncthreads();

    // =============================== write out ===============================
    float* ot = out + (size_t)b * Ln;
    for (int k = threadIdx.x; k < Ln; k += NTHREADS)
        ot[k] = (k < len) ? (float)tags[k] : 0.f;
    if (threadIdx.x == 0) out[(size_t)Bn * Ln + b] = s_best;
}

// ---------------------------------------------------------------------------
extern "C" void kernel_launch(void* const* d_in, const int* in_sizes, int n_in,
                              void* d_out, int out_size)
{
    const float* x    = (const float*)d_in[0];  // encoder_output [B,L,H2]
    const void*  mask = d_in[1];                // mask [B,L]
    const float* W    = (const float*)d_in[2];  // [T,H2]
    const float* bias = (const float*)d_in[3];  // [T]
    const float* st   = (const float*)d_in[4];  // start_transitions [T]
    const float* en   = (const float*)d_in[5];  // end_transitions [T]
    const float* tr   = (const float*)d_in[6];  // transitions [T,T]
    float* out = (float*)d_out;                 // tags [B*L] then best_score [B]

    cudaFuncSetAttribute(fused_kernel,
                         cudaFuncAttributeMaxDynamicSharedMemorySize, DYN_BYTES);
    fused_kernel<<<Bn, NTHREADS, DYN_BYTES>>>(x, mask, W, bias, st, en, tr, out);
}

// round 9
// speedup vs baseline: 1.8039x; 1.2945x over previous
#include <cuda_runtime.h>
#include <cstdint>

#define Bn 128
#define Ln 1024
#define Hn 1024
#define Tn 9
#define NEG_INF (-3.0e38f)

typedef unsigned long long u64;

// ---- f32x2 packed-FMA helpers (sm_103a FFMA2; only reachable via PTX) ----
__device__ __forceinline__ u64 ffma2(u64 a, u64 b, u64 c) {
    u64 d;
    asm("fma.rn.f32x2 %0, %1, %2, %3;" : "=l"(d) : "l"(a), "l"(b), "l"(c));
    return d;
}
__device__ __forceinline__ void upk(u64 v, float& lo, float& hi) {
    asm("mov.b64 {%0, %1}, %2;" : "=f"(lo), "=f"(hi) : "l"(v));
}

// dynamic smem: se = float[Ln*12 + 64] (emissions, overwritten by score vecs),
//               part = float[8*32*40], hist8 = uint8[Ln*16]
#define SE_F (Ln * 12 + 64)
#define PART_F (8 * 32 * 40)
#define HIST_B (Ln * 16)
#define DYN_BYTES (SE_F * 4 + PART_F * 4 + HIST_B)

// ---------------------------------------------------------------------------
// Fused kernel (round-5 structure + L2 prefetch in emit):
//   Phase A: 8 warps, 4 rows/warp/tile, double-buffered x loads, f32x2 FMA,
//            + prefetch.global.L2 4-5 chunks ahead (register-free MLP).
//   Phase B: warp 0 slim Viterbi forward; score vectors overwrite emissions.
//   Phase C: 256 threads compute backpointers in parallel (bit-identical).
//   Phase D: backtrace + coalesced writeout.
// ---------------------------------------------------------------------------
__global__ __launch_bounds__(256, 1) void fused_kernel(
    const float* __restrict__ x, const void* __restrict__ mask_raw,
    const float* __restrict__ W, const float* __restrict__ bias,
    const float* __restrict__ startT, const float* __restrict__ endT,
    const float* __restrict__ trans, float* __restrict__ out)
{
    extern __shared__ __align__(16) float dyn[];
    float* se = dyn;                                 // [Ln][12] emissions/scores
    float* part = dyn + SE_F;                        // [8][32][40] reduce scratch
    uint8_t* hist8 = (uint8_t*)(part + PART_F);      // [Ln][16] backpointers

    __shared__ float ttr[Tn * Tn];
    __shared__ uint8_t tags[Ln];
    __shared__ int s_len, s_lasttag;
    __shared__ float s_best;

    const int b = blockIdx.x;
    const int warp = threadIdx.x >> 5;
    const int lane = threadIdx.x & 31;

    if (threadIdx.x < Tn * Tn) ttr[threadIdx.x] = trans[threadIdx.x];

    // =============================== Phase A: emit ===========================
    const float bias_a = bias[lane % Tn];
    const float bias_b = bias[(lane + 32) % Tn];    // lanes < 4
    const int dst_a = (lane / 9) * 12 + (lane % 9); // s -> (s/9)*12 + s%9
    const int dst_b = ((lane + 32) / 9) * 12 + ((lane + 32) % 9);

    const ulonglong2* X = (const ulonglong2*)(x + (size_t)b * Ln * Hn);
    float* pw = part + (warp * 32 + lane) * 40;
    const float* pb = part + warp * 32 * 40;

    ulonglong2 va[4], vb[4];
    {   // preload tile 0, chunk 0
        const int row0 = warp * 4;
#pragma unroll
        for (int r = 0; r < 4; r++) va[r] = __ldcs(X + (row0 + r) * 256 + lane);
    }

    for (int g = 0; g < 32; g++) {
        const int row0 = g * 32 + warp * 4;
        const int row0n = (g < 31) ? row0 + 32 : row0;  // next tile (clamped)

        u64 acc[4][Tn];
#pragma unroll
        for (int r = 0; r < 4; r++)
#pragma unroll
            for (int t = 0; t < Tn; t++) acc[r][t] = 0ull;

#pragma unroll
        for (int c = 0; c < 8; c += 2) {
            // --- L2 prefetch chunks c+4, c+5 (register-free latency hiding) ---
            {
                const int pr0 = (c + 4 < 8) ? row0 : row0n;
                const int pc0 = (c + 4) & 7;
                const int pr1 = (c + 5 < 8) ? row0 : row0n;
                const int pc1 = (c + 5) & 7;
#pragma unroll
                for (int r = 0; r < 4; r++) {
                    asm volatile("prefetch.global.L2 [%0];"
                                 :: "l"(X + (pr0 + r) * 256 + lane + 32 * pc0));
                    asm volatile("prefetch.global.L2 [%0];"
                                 :: "l"(X + (pr1 + r) * 256 + lane + 32 * pc1));
                }
            }
            // prefetch chunk c+1 into vb, compute va (chunk c)
#pragma unroll
            for (int r = 0; r < 4; r++)
                vb[r] = __ldcs(X + (row0 + r) * 256 + lane + 32 * (c + 1));
            {
                const int k = (lane + 32 * c) * 4;
#pragma unroll
                for (int t = 0; t < Tn; t++) {
                    const ulonglong2 w = *(const ulonglong2*)(W + t * Hn + k);
#pragma unroll
                    for (int r = 0; r < 4; r++) {
                        acc[r][t] = ffma2(va[r].x, w.x, acc[r][t]);
                        acc[r][t] = ffma2(va[r].y, w.y, acc[r][t]);
                    }
                }
            }
            // load chunk c+2 (or next tile's chunk 0) into va, compute vb
            const int cn = (c + 2 < 8) ? (c + 2) : 0;
            const int rown = (c + 2 < 8) ? row0 : row0n;
#pragma unroll
            for (int r = 0; r < 4; r++)
                va[r] = __ldcs(X + (rown + r) * 256 + lane + 32 * cn);
            {
                const int k = (lane + 32 * (c + 1)) * 4;
#pragma unroll
                for (int t = 0; t < Tn; t++) {
                    const ulonglong2 w = *(const ulonglong2*)(W + t * Hn + k);
#pragma unroll
                    for (int r = 0; r < 4; r++) {
                        acc[r][t] = ffma2(vb[r].x, w.x, acc[r][t]);
                        acc[r][t] = ffma2(vb[r].y, w.y, acc[r][t]);
                    }
                }
            }
        }

        // pair-sum packed halves -> 36 per-lane partials
#pragma unroll
        for (int r = 0; r < 4; r++)
#pragma unroll
            for (int t = 0; t < Tn; t++) {
                float lo, hi;
                upk(acc[r][t], lo, hi);
                pw[r * Tn + t] = lo + hi;
            }
        __syncwarp();

        // transpose reduce: lane s sums column s (s = r*9+t) over 32 lanes
        {
            float a0 = 0.f, a1 = 0.f, a2 = 0.f, a3 = 0.f;
#pragma unroll
            for (int L = 0; L < 32; L += 4) {
                a0 += pb[(L + 0) * 40 + lane];
                a1 += pb[(L + 1) * 40 + lane];
                a2 += pb[(L + 2) * 40 + lane];
                a3 += pb[(L + 3) * 40 + lane];
            }
            se[row0 * 12 + dst_a] = (a0 + a1) + (a2 + a3) + bias_a;
        }
        if (lane < 4) {
            const int s = lane + 32;
            float a0 = 0.f, a1 = 0.f, a2 = 0.f, a3 = 0.f;
#pragma unroll
            for (int L = 0; L < 32; L += 4) {
                a0 += pb[(L + 0) * 40 + s];
                a1 += pb[(L + 1) * 40 + s];
                a2 += pb[(L + 2) * 40 + s];
                a3 += pb[(L + 3) * 40 + s];
            }
            se[row0 * 12 + dst_b] = (a0 + a1) + (a2 + a3) + bias_b;
        }
        __syncwarp();
    }
    __syncthreads();

    // ======================= Phase B: forward (warp 0) =======================
    if (warp == 0) {
        const int j = lane;

        // mask dtype detection + length (prefix mask)
        const unsigned* mw = (const unsigned*)mask_raw;
        const unsigned first = mw[0];
        const bool word_mask = (first == 1u) || (first == 0x3F800000u);
        int len = 0;
        if (word_mask) {
            const unsigned* m = mw + (size_t)b * Ln;
            for (int k = lane; k < Ln; k += 32) len += (m[k] != 0u);
        } else {
            const uint8_t* m = (const uint8_t*)mask_raw + (size_t)b * Ln;
            for (int k = lane; k < Ln; k += 32) len += (m[k] != 0);
        }
#pragma unroll
        for (int o = 16; o; o >>= 1) len += __shfl_xor_sync(0xffffffffu, len, o);

        const int jc = (j < Tn) ? j : 8;
        const int hidx = (j < 11) ? j : 11;  // lanes >= 9 -> pad cols 9..11
        float tcol[Tn];
#pragma unroll
        for (int i = 0; i < Tn; i++) tcol[i] = ttr[i * Tn + jc];

        float score = (j < Tn) ? startT[j] + se[j] : NEG_INF;

        const float* erow = se + 12;  // emission row l (starts at l=1)
        float* srow = se;             // score-vector row l-1

        for (int l = 1; l < len; l++) {
            srow[hidx] = score;  // store sv_{l-1} over consumed emission row
            asm volatile("" ::: "memory");
            const float4 sa = *(const float4*)(srow);
            const float4 sb = *(const float4*)(srow + 4);
            const float s8v = srow[8];
            const float e = erow[j];

            const float cv0 = sa.x + tcol[0];
            const float cv1 = sa.y + tcol[1];
            const float cv2 = sa.z + tcol[2];
            const float cv3 = sa.w + tcol[3];
            const float cv4 = sb.x + tcol[4];
            const float cv5 = sb.y + tcol[5];
            const float cv6 = sb.z + tcol[6];
            const float cv7 = sb.w + tcol[7];
            const float cv8 = s8v + tcol[8];

            const float m0 = fmaxf(cv0, cv1);
            const float m1 = fmaxf(cv2, cv3);
            const float m2 = fmaxf(cv4, cv5);
            const float m3 = fmaxf(cv6, cv7);
            const float best = fmaxf(fmaxf(fmaxf(m0, m1), fmaxf(m2, m3)), cv8);

            score = best + e;
            srow += 12;
            erow += 12;
        }

        // final scores + argmax over states (exchange via row len-1)
        const float fin = (j < Tn) ? score + endT[j] : NEG_INF;
        srow[hidx] = fin;
        asm volatile("" ::: "memory");
        const float4 fa = *(const float4*)(srow);
        const float4 fb = *(const float4*)(srow + 4);
        const float f8v = srow[8];
        const float f0 = fmaxf(fa.x, fa.y);
        const float f1 = fmaxf(fa.z, fa.w);
        const float f2 = fmaxf(fb.x, fb.y);
        const float f3 = fmaxf(fb.z, fb.w);
        const float best_f = fmaxf(fmaxf(fmaxf(f0, f1), fmaxf(f2, f3)), f8v);
        const int g0 = (fa.x == best_f) ? 0 : 9;
        const int g1 = (fa.y == best_f) ? 1 : 9;
        const int g2 = (fa.z == best_f) ? 2 : 9;
        const int g3 = (fa.w == best_f) ? 3 : 9;
        const int g4 = (fb.x == best_f) ? 4 : 9;
        const int g5 = (fb.y == best_f) ? 5 : 9;
        const int g6 = (fb.z == best_f) ? 6 : 9;
        const int g7 = (fb.w == best_f) ? 7 : 9;
        const int g8 = (f8v == best_f) ? 8 : 9;
        const int h0 = min(min(g0, g1), min(g2, g3));
        const int h1 = min(min(g4, g5), min(g6, g7));
        if (lane == 0) {
            s_len = len;
            s_best = best_f;
            s_lasttag = min(min(h0, h1), g8);
        }
    }
    __syncthreads();

    // ================= Phase C: parallel backpointers (all threads) ==========
    const int len = s_len;
    for (int l = 1 + (int)threadIdx.x; l < len; l += 256) {
        const float* sv = se + (l - 1) * 12;
        const float p0 = sv[0], p1 = sv[1], p2 = sv[2], p3 = sv[3], p4 = sv[4];
        const float p5 = sv[5], p6 = sv[6], p7 = sv[7], p8 = sv[8];
#pragma unroll
        for (int j = 0; j < Tn; j++) {
            const float cv0 = p0 + ttr[0 * Tn + j];
            const float cv1 = p1 + ttr[1 * Tn + j];
            const float cv2 = p2 + ttr[2 * Tn + j];
            const float cv3 = p3 + ttr[3 * Tn + j];
            const float cv4 = p4 + ttr[4 * Tn + j];
            const float cv5 = p5 + ttr[5 * Tn + j];
            const float cv6 = p6 + ttr[6 * Tn + j];
            const float cv7 = p7 + ttr[7 * Tn + j];
            const float cv8 = p8 + ttr[8 * Tn + j];
            const float m0 = fmaxf(cv0, cv1);
            const float m1 = fmaxf(cv2, cv3);
            const float m2 = fmaxf(cv4, cv5);
            const float m3 = fmaxf(cv6, cv7);
            const float best = fmaxf(fmaxf(fmaxf(m0, m1), fmaxf(m2, m3)), cv8);
            const int e0 = (cv0 == best) ? 0 : 9;
            const int e1 = (cv1 == best) ? 1 : 9;
            const int e2 = (cv2 == best) ? 2 : 9;
            const int e3 = (cv3 == best) ? 3 : 9;
            const int e4 = (cv4 == best) ? 4 : 9;
            const int e5 = (cv5 == best) ? 5 : 9;
            const int e6 = (cv6 == best) ? 6 : 9;
            const int e7 = (cv7 == best) ? 7 : 9;
            const int e8 = (cv8 == best) ? 8 : 9;
            const int a0 = min(min(e0, e1), min(e2, e3));
            const int a1 = min(min(e4, e5), min(e6, e7));
            hist8[l * 16 + j] = (uint8_t)min(min(a0, a1), e8);
        }
    }
    __syncthreads();

    // ===================== Phase D: backtrace (thread 0) =====================
    if (threadIdx.x == 0) {
        int tag = s_lasttag;
        tags[len - 1] = (uint8_t)tag;
        for (int l = len - 2; l >= 0; --l) {
            tag = (int)hist8[(l + 1) * 16 + tag];
            tags[l] = (uint8_t)tag;
        }
    }
    __syncthreads();

    // =============================== write out ===============================
    float* ot = out + (size_t)b * Ln;
    for (int k = threadIdx.x; k < Ln; k += 256)
        ot[k] = (k < len) ? (float)tags[k] : 0.f;
    if (threadIdx.x == 0) out[(size_t)Bn * Ln + b] = s_best;
}

// ---------------------------------------------------------------------------
extern "C" void kernel_launch(void* const* d_in, const int* in_sizes, int n_in,
                              void* d_out, int out_size)
{
    const float* x    = (const float*)d_in[0];  // encoder_output [B,L,H2]
    const void*  mask = d_in[1];                // mask [B,L]
    const float* W    = (const float*)d_in[2];  // [T,H2]
    const float* bias = (const float*)d_in[3];  // [T]
    const float* st   = (const float*)d_in[4];  // start_transitions [T]
    const float* en   = (const float*)d_in[5];  // end_transitions [T]
    const float* tr   = (const float*)d_in[6];  // transitions [T,T]
    float* out = (float*)d_out;                 // tags [B*L] then best_score [B]

    cudaFuncSetAttribute(fused_kernel,
                         cudaFuncAttributeMaxDynamicSharedMemorySize, DYN_BYTES);
    fused_kernel<<<Bn, 256, DYN_BYTES>>>(x, mask, W, bias, st, en, tr, out);
}

// round 11
// speedup vs baseline: 1.9465x; 1.0790x over previous
#include <cuda_runtime.h>
#include <cstdint>

#define Bn 128
#define Ln 1024
#define Hn 1024
#define Tn 9
#define NEG_INF (-3.0e38f)

typedef unsigned long long u64;

// ---- f32x2 packed-FMA helpers (sm_103a FFMA2; only reachable via PTX) ----
__device__ __forceinline__ u64 ffma2(u64 a, u64 b, u64 c) {
    u64 d;
    asm("fma.rn.f32x2 %0, %1, %2, %3;" : "=l"(d) : "l"(a), "l"(b), "l"(c));
    return d;
}
__device__ __forceinline__ void upk(u64 v, float& lo, float& hi) {
    asm("mov.b64 {%0, %1}, %2;" : "=f"(lo), "=f"(hi) : "l"(v));
}

// tag-map lookup: map packed as u64 (entries 0..7, one byte each) + byte for 8
__device__ __forceinline__ int mlook(u64 lo, int hi, int idx) {
    return (idx >= 8) ? hi : (int)((lo >> (idx * 8)) & 0xFF);
}

// dynamic smem: se = float[Ln*12 + 64], part = float[8*32*40], hist8 = u8[Ln*16]
#define SE_F (Ln * 12 + 64)
#define PART_F (8 * 32 * 40)
#define HIST_B (Ln * 16)
#define DYN_BYTES (SE_F * 4 + PART_F * 4 + HIST_B)

// ---------------------------------------------------------------------------
// Fused kernel:
//   Phase A: emit GEMM, 8 warps, double-buffered x + full-tile-ahead L2
//            prefetch, f32x2 FMA, transpose-reduce.
//   Phase B: warp 0 slim Viterbi forward (score vecs overwrite emissions).
//   Phase C: 256 threads compute backpointers in parallel + identity padding.
//   Phase D: PARALLEL backtrace via suffix composition of tag maps.
// ---------------------------------------------------------------------------
__global__ __launch_bounds__(256, 1) void fused_kernel(
    const float* __restrict__ x, const void* __restrict__ mask_raw,
    const float* __restrict__ W, const float* __restrict__ bias,
    const float* __restrict__ startT, const float* __restrict__ endT,
    const float* __restrict__ trans, float* __restrict__ out)
{
    extern __shared__ __align__(16) float dyn[];
    float* se = dyn;                                 // [Ln][12] emissions/scores
    float* part = dyn + SE_F;                        // [8][32][40] reduce scratch
    uint8_t* hist8 = (uint8_t*)(part + PART_F);      // [Ln][16] backpointer maps
    uint8_t* chmap = (uint8_t*)part;                 // [128][16] chunk maps (reuses part)

    __shared__ float ttr[Tn * Tn];
    __shared__ uint8_t tags[Ln];
    __shared__ int s_len, s_lasttag;
    __shared__ float s_best;

    const int b = blockIdx.x;
    const int warp = threadIdx.x >> 5;
    const int lane = threadIdx.x & 31;

    if (threadIdx.x < Tn * Tn) ttr[threadIdx.x] = trans[threadIdx.x];

    // =============================== Phase A: emit ===========================
    const float bias_a = bias[lane % Tn];
    const float bias_b = bias[(lane + 32) % Tn];    // lanes < 4
    const int dst_a = (lane / 9) * 12 + (lane % 9); // s -> (s/9)*12 + s%9
    const int dst_b = ((lane + 32) / 9) * 12 + ((lane + 32) % 9);

    const ulonglong2* X = (const ulonglong2*)(x + (size_t)b * Ln * Hn);
    float* pw = part + (warp * 32 + lane) * 40;
    const float* pb = part + warp * 32 * 40;

    ulonglong2 va[4], vb[4];
    {   // preload tile 0, chunk 0
        const int row0 = warp * 4;
#pragma unroll
        for (int r = 0; r < 4; r++) va[r] = __ldcs(X + (row0 + r) * 256 + lane);
    }

    for (int g = 0; g < 32; g++) {
        const int row0 = g * 32 + warp * 4;
        const int row0n = (g < 31) ? row0 + 32 : row0;  // next tile (clamped)

        u64 acc[4][Tn];
#pragma unroll
        for (int r = 0; r < 4; r++)
#pragma unroll
            for (int t = 0; t < Tn; t++) acc[r][t] = 0ull;

#pragma unroll
        for (int c = 0; c < 8; c += 2) {
            // --- L2 prefetch: NEXT TILE's chunks c, c+1 (~1 tile of lead) ---
#pragma unroll
            for (int r = 0; r < 4; r++) {
                asm volatile("prefetch.global.L2 [%0];"
                             :: "l"(X + (row0n + r) * 256 + lane + 32 * c));
                asm volatile("prefetch.global.L2 [%0];"
                             :: "l"(X + (row0n + r) * 256 + lane + 32 * (c + 1)));
            }
            // prefetch chunk c+1 into vb, compute va (chunk c)
#pragma unroll
            for (int r = 0; r < 4; r++)
                vb[r] = __ldcs(X + (row0 + r) * 256 + lane + 32 * (c + 1));
            {
                const int k = (lane + 32 * c) * 4;
#pragma unroll
                for (int t = 0; t < Tn; t++) {
                    const ulonglong2 w = *(const ulonglong2*)(W + t * Hn + k);
#pragma unroll
                    for (int r = 0; r < 4; r++) {
                        acc[r][t] = ffma2(va[r].x, w.x, acc[r][t]);
                        acc[r][t] = ffma2(va[r].y, w.y, acc[r][t]);
                    }
                }
            }
            // load chunk c+2 (or next tile's chunk 0) into va, compute vb
            const int cn = (c + 2 < 8) ? (c + 2) : 0;
            const int rown = (c + 2 < 8) ? row0 : row0n;
#pragma unroll
            for (int r = 0; r < 4; r++)
                va[r] = __ldcs(X + (rown + r) * 256 + lane + 32 * cn);
            {
                const int k = (lane + 32 * (c + 1)) * 4;
#pragma unroll
                for (int t = 0; t < Tn; t++) {
                    const ulonglong2 w = *(const ulonglong2*)(W + t * Hn + k);
#pragma unroll
                    for (int r = 0; r < 4; r++) {
                        acc[r][t] = ffma2(vb[r].x, w.x, acc[r][t]);
                        acc[r][t] = ffma2(vb[r].y, w.y, acc[r][t]);
                    }
                }
            }
        }

        // pair-sum packed halves -> 36 per-lane partials
#pragma unroll
        for (int r = 0; r < 4; r++)
#pragma unroll
            for (int t = 0; t < Tn; t++) {
                float lo, hi;
                upk(acc[r][t], lo, hi);
                pw[r * Tn + t] = lo + hi;
            }
        __syncwarp();

        // transpose reduce: lane s sums column s (s = r*9+t) over 32 lanes
        {
            float a0 = 0.f, a1 = 0.f, a2 = 0.f, a3 = 0.f;
#pragma unroll
            for (int L = 0; L < 32; L += 4) {
                a0 += pb[(L + 0) * 40 + lane];
                a1 += pb[(L + 1) * 40 + lane];
                a2 += pb[(L + 2) * 40 + lane];
                a3 += pb[(L + 3) * 40 + lane];
            }
            se[row0 * 12 + dst_a] = (a0 + a1) + (a2 + a3) + bias_a;
        }
        if (lane < 4) {
            const int s = lane + 32;
            float a0 = 0.f, a1 = 0.f, a2 = 0.f, a3 = 0.f;
#pragma unroll
            for (int L = 0; L < 32; L += 4) {
                a0 += pb[(L + 0) * 40 + s];
                a1 += pb[(L + 1) * 40 + s];
                a2 += pb[(L + 2) * 40 + s];
                a3 += pb[(L + 3) * 40 + s];
            }
            se[row0 * 12 + dst_b] = (a0 + a1) + (a2 + a3) + bias_b;
        }
        __syncwarp();
    }
    __syncthreads();

    // ======================= Phase B: forward (warp 0) =======================
    if (warp == 0) {
        const int j = lane;

        // mask dtype detection + length (prefix mask)
        const unsigned* mw = (const unsigned*)mask_raw;
        const unsigned first = mw[0];
        const bool word_mask = (first == 1u) || (first == 0x3F800000u);
        int len = 0;
        if (word_mask) {
            const unsigned* m = mw + (size_t)b * Ln;
            for (int k = lane; k < Ln; k += 32) len += (m[k] != 0u);
        } else {
            const uint8_t* m = (const uint8_t*)mask_raw + (size_t)b * Ln;
            for (int k = lane; k < Ln; k += 32) len += (m[k] != 0);
        }
#pragma unroll
        for (int o = 16; o; o >>= 1) len += __shfl_xor_sync(0xffffffffu, len, o);

        const int jc = (j < Tn) ? j : 8;
        const int hidx = (j < 11) ? j : 11;  // lanes >= 9 -> pad cols 9..11
        float tcol[Tn];
#pragma unroll
        for (int i = 0; i < Tn; i++) tcol[i] = ttr[i * Tn + jc];

        float score = (j < Tn) ? startT[j] + se[j] : NEG_INF;

        const float* erow = se + 12;  // emission row l (starts at l=1)
        float* srow = se;             // score-vector row l-1

        for (int l = 1; l < len; l++) {
            srow[hidx] = score;  // store sv_{l-1} over consumed emission row
            asm volatile("" ::: "memory");
            const float4 sa = *(const float4*)(srow);
            const float4 sb = *(const float4*)(srow + 4);
            const float s8v = srow[8];
            const float e = erow[j];

            const float cv0 = sa.x + tcol[0];
            const float cv1 = sa.y + tcol[1];
            const float cv2 = sa.z + tcol[2];
            const float cv3 = sa.w + tcol[3];
            const float cv4 = sb.x + tcol[4];
            const float cv5 = sb.y + tcol[5];
            const float cv6 = sb.z + tcol[6];
            const float cv7 = sb.w + tcol[7];
            const float cv8 = s8v + tcol[8];

            const float m0 = fmaxf(cv0, cv1);
            const float m1 = fmaxf(cv2, cv3);
            const float m2 = fmaxf(cv4, cv5);
            const float m3 = fmaxf(cv6, cv7);
            const float best = fmaxf(fmaxf(fmaxf(m0, m1), fmaxf(m2, m3)), cv8);

            score = best + e;
            srow += 12;
            erow += 12;
        }

        // final scores + argmax over states (exchange via row len-1)
        const float fin = (j < Tn) ? score + endT[j] : NEG_INF;
        srow[hidx] = fin;
        asm volatile("" ::: "memory");
        const float4 fa = *(const float4*)(srow);
        const float4 fb = *(const float4*)(srow + 4);
        const float f8v = srow[8];
        const float f0 = fmaxf(fa.x, fa.y);
        const float f1 = fmaxf(fa.z, fa.w);
        const float f2 = fmaxf(fb.x, fb.y);
        const float f3 = fmaxf(fb.z, fb.w);
        const float best_f = fmaxf(fmaxf(fmaxf(f0, f1), fmaxf(f2, f3)), f8v);
        const int g0 = (fa.x == best_f) ? 0 : 9;
        const int g1 = (fa.y == best_f) ? 1 : 9;
        const int g2 = (fa.z == best_f) ? 2 : 9;
        const int g3 = (fa.w == best_f) ? 3 : 9;
        const int g4 = (fb.x == best_f) ? 4 : 9;
        const int g5 = (fb.y == best_f) ? 5 : 9;
        const int g6 = (fb.z == best_f) ? 6 : 9;
        const int g7 = (fb.w == best_f) ? 7 : 9;
        const int g8 = (f8v == best_f) ? 8 : 9;
        const int h0 = min(min(g0, g1), min(g2, g3));
        const int h1 = min(min(g4, g5), min(g6, g7));
        if (lane == 0) {
            s_len = len;
            s_best = best_f;
            s_lasttag = min(min(h0, h1), g8);
        }
    }
    __syncthreads();

    // ================= Phase C: parallel backpointers (all threads) ==========
    const int len = s_len;
    for (int l = 1 + (int)threadIdx.x; l < len; l += 256) {
        const float* sv = se + (l - 1) * 12;
        const float p0 = sv[0], p1 = sv[1], p2 = sv[2], p3 = sv[3], p4 = sv[4];
        const float p5 = sv[5], p6 = sv[6], p7 = sv[7], p8 = sv[8];
#pragma unroll
        for (int j = 0; j < Tn; j++) {
            const float cv0 = p0 + ttr[0 * Tn + j];
            const float cv1 = p1 + ttr[1 * Tn + j];
            const float cv2 = p2 + ttr[2 * Tn + j];
            const float cv3 = p3 + ttr[3 * Tn + j];
            const float cv4 = p4 + ttr[4 * Tn + j];
            const float cv5 = p5 + ttr[5 * Tn + j];
            const float cv6 = p6 + ttr[6 * Tn + j];
            const float cv7 = p7 + ttr[7 * Tn + j];
            const float cv8 = p8 + ttr[8 * Tn + j];
            const float m0 = fmaxf(cv0, cv1);
            const float m1 = fmaxf(cv2, cv3);
            const float m2 = fmaxf(cv4, cv5);
            const float m3 = fmaxf(cv6, cv7);
            const float best = fmaxf(fmaxf(fmaxf(m0, m1), fmaxf(m2, m3)), cv8);
            const int e0 = (cv0 == best) ? 0 : 9;
            const int e1 = (cv1 == best) ? 1 : 9;
            const int e2 = (cv2 == best) ? 2 : 9;
            const int e3 = (cv3 == best) ? 3 : 9;
            const int e4 = (cv4 == best) ? 4 : 9;
            const int e5 = (cv5 == best) ? 5 : 9;
            const int e6 = (cv6 == best) ? 6 : 9;
            const int e7 = (cv7 == best) ? 7 : 9;
            const int e8 = (cv8 == best) ? 8 : 9;
            const int a0 = min(min(e0, e1), min(e2, e3));
            const int a1 = min(min(e4, e5), min(e6, e7));
            hist8[l * 16 + j] = (uint8_t)min(min(a0, a1), e8);
        }
    }
    // identity maps for l = 0 and l >= len (frozen steps carry same tag)
    for (int l = (int)threadIdx.x; l < Ln; l += 256) {
        if (l == 0 || l >= len) {
#pragma unroll
            for (int j = 0; j < Tn; j++) hist8[l * 16 + j] = (uint8_t)j;
        }
    }
    __syncthreads();

    // ========== Phase D: parallel backtrace via suffix map composition =======
    // tags[l] = (g_{l+1} o g_{l+2} o ... o g_{1023})(last_tag), g = hist8 rows.
    const int t = (int)threadIdx.x;
    u64 mlo = 0; int mhi = 0;

    // D1: chunk maps C_t = g_{8t} o ... o g_{8t+7} (128 threads)
    if (t < 128) {
        const uint8_t* g7 = hist8 + (8 * t + 7) * 16;
#pragma unroll
        for (int j = 0; j < 8; j++) mlo |= (u64)g7[j] << (8 * j);
        mhi = g7[8];
#pragma unroll
        for (int k = 6; k >= 0; k--) {
            const uint8_t* gk = hist8 + (8 * t + k) * 16;
            u64 nl = 0;
#pragma unroll
            for (int j = 0; j < 8; j++)
                nl |= (u64)gk[(int)((mlo >> (8 * j)) & 0xFF)] << (8 * j);
            const int nh = gk[mhi];
            mlo = nl; mhi = nh;
        }
        *(u64*)(chmap + t * 16) = mlo;
        chmap[t * 16 + 8] = (uint8_t)mhi;
    }
    __syncthreads();

    // D2: Hillis-Steele suffix scan: S_t = C_t o C_{t+1} o ... o C_{127}
    for (int off = 1; off < 128; off <<= 1) {
        u64 nlo = 0; int nhi = 0;
        const bool act = (t < 128) && (t + off < 128);
        if (act) {
            nlo = *(const u64*)(chmap + (t + off) * 16);
            nhi = chmap[(t + off) * 16 + 8];
        }
        __syncthreads();
        if (act) {
            u64 rlo = 0;
#pragma unroll
            for (int j = 0; j < 8; j++) {
                const int idx = (int)((nlo >> (8 * j)) & 0xFF);
                rlo |= (u64)mlook(mlo, mhi, idx) << (8 * j);
            }
            const int rhi = mlook(mlo, mhi, nhi);
            mlo = rlo; mhi = rhi;
            *(u64*)(chmap + t * 16) = mlo;
            chmap[t * 16 + 8] = (uint8_t)mhi;
        }
        __syncthreads();
    }

    // D3: emit tags per chunk (thread t handles l in [8t, 8t+8))
    if (t < 128) {
        int cur;
        if (t == 127) cur = s_lasttag;
        else cur = (int)chmap[(t + 1) * 16 + s_lasttag];  // S_{t+1}(last)
        tags[8 * t + 7] = (uint8_t)cur;
#pragma unroll
        for (int k = 6; k >= 0; k--) {
            cur = (int)hist8[(8 * t + k + 1) * 16 + cur];
            tags[8 * t + k] = (uint8_t)cur;
        }
    }
    __syncthreads();

    // =============================== write out ===============================
    float* ot = out + (size_t)b * Ln;
    for (int k = threadIdx.x; k < Ln; k += 256)
        ot[k] = (k < len) ? (float)tags[k] : 0.f;
    if (threadIdx.x == 0) out[(size_t)Bn * Ln + b] = s_best;
}

// ---------------------------------------------------------------------------
extern "C" void kernel_launch(void* const* d_in, const int* in_sizes, int n_in,
                              void* d_out, int out_size)
{
    const float* x    = (const float*)d_in[0];  // encoder_output [B,L,H2]
    const void*  mask = d_in[1];                // mask [B,L]
    const float* W    = (const float*)d_in[2];  // [T,H2]
    const float* bias = (const float*)d_in[3];  // [T]
    const float* st   = (const float*)d_in[4];  // start_transitions [T]
    const float* en   = (const float*)d_in[5];  // end_transitions [T]
    const float* tr   = (const float*)d_in[6];  // transitions [T,T]
    float* out = (float*)d_out;                 // tags [B*L] then best_score [B]

    cudaFuncSetAttribute(fused_kernel,
                         cudaFuncAttributeMaxDynamicSharedMemorySize, DYN_BYTES);
    fused_kernel<<<Bn, 256, DYN_BYTES>>>(x, mask, W, bias, st, en, tr, out);
}

// round 14
// speedup vs baseline: 2.2605x; 1.1613x over previous
#include <cuda_runtime.h>
#include <cstdint>

#define Bn 128
#define Ln 1024
#define Hn 1024
#define Tn 9
#define NEG_INF (-3.0e38f)

#define NPROD 7           // producer warps (warp 7 = consumer)
#define GROWS 28          // rows per group (7 warps * 4 rows)
#define NGRP 37           // ceil(1024 / 28)

typedef unsigned long long u64;

// ---- f32x2 packed-FMA helpers (sm_103a FFMA2; only reachable via PTX) ----
__device__ __forceinline__ u64 ffma2(u64 a, u64 b, u64 c) {
    u64 d;
    asm("fma.rn.f32x2 %0, %1, %2, %3;" : "=l"(d) : "l"(a), "l"(b), "l"(c));
    return d;
}
__device__ __forceinline__ void upk(u64 v, float& lo, float& hi) {
    asm("mov.b64 {%0, %1}, %2;" : "=f"(lo), "=f"(hi) : "l"(v));
}

// tag-map lookup: map packed as u64 (entries 0..7, one byte each) + byte for 8
__device__ __forceinline__ int mlook(u64 lo, int hi, int idx) {
    return (idx >= 8) ? hi : (int)((lo >> (idx * 8)) & 0xFF);
}

// dynamic smem: se = float[Ln*12 + 64], part = float[8*32*40], hist8 = u8[Ln*16]
#define SE_F (Ln * 12 + 64)
#define PART_F (8 * 32 * 40)
#define HIST_B (Ln * 16)
#define DYN_BYTES (SE_F * 4 + PART_F * 4 + HIST_B)

// ---------------------------------------------------------------------------
// Fused kernel, warp-specialized overlap:
//   warps 0-6: emit GEMM producers (28-row groups, double-buffered x loads,
//              next-group L2 prefetch, f32x2 FMA, transpose-reduce),
//              publishing groups via smem ready counters.
//   warp 7:    Viterbi forward runs CONCURRENTLY, consuming groups.
//   then: parallel backpointers, suffix-composition parallel backtrace,
//         coalesced writeout.
// ---------------------------------------------------------------------------
__global__ __launch_bounds__(256, 1) void fused_kernel(
    const float* __restrict__ x, const void* __restrict__ mask_raw,
    const float* __restrict__ W, const float* __restrict__ bias,
    const float* __restrict__ startT, const float* __restrict__ endT,
    const float* __restrict__ trans, float* __restrict__ out)
{
    extern __shared__ __align__(16) float dyn[];
    float* se = dyn;                                 // [Ln][12] emissions/scores
    float* part = dyn + SE_F;                        // [8][32][40] reduce scratch
    uint8_t* hist8 = (uint8_t*)(part + PART_F);      // [Ln][16] backpointer maps
    uint8_t* chmap = (uint8_t*)part;                 // [128][16] chunk maps (reuses part)

    __shared__ float ttr[Tn * Tn];
    __shared__ int cnt[NGRP];                        // per-group ready counters
    __shared__ uint8_t tags[Ln];
    __shared__ int s_len, s_lasttag;
    __shared__ float s_best;

    const int b = blockIdx.x;
    const int warp = threadIdx.x >> 5;
    const int lane = threadIdx.x & 31;

    if (threadIdx.x < Tn * Tn) ttr[threadIdx.x] = trans[threadIdx.x];
    if (threadIdx.x >= 128 && threadIdx.x < 128 + NGRP) cnt[threadIdx.x - 128] = 0;
    __syncthreads();   // counters + ttr visible before producers start

    if (warp < NPROD) {
        // ===================== emit (producer warps 0-6) =====================
        const float bias_a = bias[lane % Tn];
        const float bias_b = bias[(lane + 32) % Tn];    // lanes < 4
        const int dst_a = (lane / 9) * 12 + (lane % 9); // s -> (s/9)*12 + s%9
        const int dst_b = ((lane + 32) / 9) * 12 + ((lane + 32) % 9);

        const ulonglong2* X = (const ulonglong2*)(x + (size_t)b * Ln * Hn);
        float* pw = part + (warp * 32 + lane) * 40;
        const float* pb = part + warp * 32 * 40;

        ulonglong2 va[4], vb[4];
        {   // preload group 0, chunk 0
            const int row0 = warp * 4;
#pragma unroll
            for (int r = 0; r < 4; r++) va[r] = __ldcs(X + (row0 + r) * 256 + lane);
        }

        for (int g = 0; g < NGRP; g++) {
            const int row0 = g * GROWS + warp * 4;
            if (row0 < Ln) {
                const int row0n = (row0 + GROWS < Ln) ? row0 + GROWS : row0;

                u64 acc[4][Tn];
#pragma unroll
                for (int r = 0; r < 4; r++)
#pragma unroll
                    for (int t = 0; t < Tn; t++) acc[r][t] = 0ull;

#pragma unroll
                for (int c = 0; c < 8; c += 2) {
                    // --- L2 prefetch next group's chunks c, c+1 ---
#pragma unroll
                    for (int r = 0; r < 4; r++) {
                        asm volatile("prefetch.global.L2 [%0];"
                                     :: "l"(X + (row0n + r) * 256 + lane + 32 * c));
                        asm volatile("prefetch.global.L2 [%0];"
                                     :: "l"(X + (row0n + r) * 256 + lane + 32 * (c + 1)));
                    }
                    // prefetch chunk c+1 into vb, compute va (chunk c)
#pragma unroll
                    for (int r = 0; r < 4; r++)
                        vb[r] = __ldcs(X + (row0 + r) * 256 + lane + 32 * (c + 1));
                    {
                        const int k = (lane + 32 * c) * 4;
#pragma unroll
                        for (int t = 0; t < Tn; t++) {
                            const ulonglong2 w = *(const ulonglong2*)(W + t * Hn + k);
#pragma unroll
                            for (int r = 0; r < 4; r++) {
                                acc[r][t] = ffma2(va[r].x, w.x, acc[r][t]);
                                acc[r][t] = ffma2(va[r].y, w.y, acc[r][t]);
                            }
                        }
                    }
                    // load chunk c+2 (or next group's chunk 0) into va, compute vb
                    const int cn = (c + 2 < 8) ? (c + 2) : 0;
                    const int rown = (c + 2 < 8) ? row0 : row0n;
#pragma unroll
                    for (int r = 0; r < 4; r++)
                        va[r] = __ldcs(X + (rown + r) * 256 + lane + 32 * cn);
                    {
                        const int k = (lane + 32 * (c + 1)) * 4;
#pragma unroll
                        for (int t = 0; t < Tn; t++) {
                            const ulonglong2 w = *(const ulonglong2*)(W + t * Hn + k);
#pragma unroll
                            for (int r = 0; r < 4; r++) {
                                acc[r][t] = ffma2(vb[r].x, w.x, acc[r][t]);
                                acc[r][t] = ffma2(vb[r].y, w.y, acc[r][t]);
                            }
                        }
                    }
                }

                // pair-sum packed halves -> 36 per-lane partials
#pragma unroll
                for (int r = 0; r < 4; r++)
#pragma unroll
                    for (int t = 0; t < Tn; t++) {
                        float lo, hi;
                        upk(acc[r][t], lo, hi);
                        pw[r * Tn + t] = lo + hi;
                    }
                __syncwarp();

                // transpose reduce: lane s sums column s over 32 lanes
                {
                    float a0 = 0.f, a1 = 0.f, a2 = 0.f, a3 = 0.f;
#pragma unroll
                    for (int L = 0; L < 32; L += 4) {
                        a0 += pb[(L + 0) * 40 + lane];
                        a1 += pb[(L + 1) * 40 + lane];
                        a2 += pb[(L + 2) * 40 + lane];
                        a3 += pb[(L + 3) * 40 + lane];
                    }
                    se[row0 * 12 + dst_a] = (a0 + a1) + (a2 + a3) + bias_a;
                }
                if (lane < 4) {
                    const int s = lane + 32;
                    float a0 = 0.f, a1 = 0.f, a2 = 0.f, a3 = 0.f;
#pragma unroll
                    for (int L = 0; L < 32; L += 4) {
                        a0 += pb[(L + 0) * 40 + s];
                        a1 += pb[(L + 1) * 40 + s];
                        a2 += pb[(L + 2) * 40 + s];
                        a3 += pb[(L + 3) * 40 + s];
                    }
                    se[row0 * 12 + dst_b] = (a0 + a1) + (a2 + a3) + bias_b;
                }
                __syncwarp();
            }
            // publish group g (release)
            if (lane == 0) {
                __threadfence_block();
                atomicAdd(&cnt[g], 1);
            }
        }
    } else {
        // ================= Viterbi forward (consumer, warp 7) ================
        const int j = lane;

        // mask dtype detection + length (independent of emit)
        const unsigned* mw = (const unsigned*)mask_raw;
        const unsigned first = mw[0];
        const bool word_mask = (first == 1u) || (first == 0x3F800000u);
        int len = 0;
        if (word_mask) {
            const unsigned* m = mw + (size_t)b * Ln;
            for (int k = lane; k < Ln; k += 32) len += (m[k] != 0u);
        } else {
            const uint8_t* m = (const uint8_t*)mask_raw + (size_t)b * Ln;
            for (int k = lane; k < Ln; k += 32) len += (m[k] != 0);
        }
#pragma unroll
        for (int o = 16; o; o >>= 1) len += __shfl_xor_sync(0xffffffffu, len, o);

        const int jc = (j < Tn) ? j : 8;
        const int hidx = (j < 11) ? j : 11;  // lanes >= 9 -> pad cols 9..11
        float tcol[Tn];
#pragma unroll
        for (int i = 0; i < Tn; i++) tcol[i] = trans[i * Tn + jc];  // global (ttr raced)
        const float stj = (j < Tn) ? startT[j] : 0.f;

        // wait for group 0 (acquire)
        while (*(volatile int*)&cnt[0] < NPROD) { }
        __threadfence_block();

        float score = (j < Tn) ? stj + se[j] : NEG_INF;

        const float* erow = se + 12;  // emission row l (starts at l=1)
        float* srow = se;             // score-vector row l-1
        int bound = GROWS, gn = 1;

        for (int l = 1; l < len; l++) {
            if (l >= bound) {         // entering group gn: wait until ready
                while (*(volatile int*)&cnt[gn] < NPROD) { }
                __threadfence_block();
                gn++;
                bound += GROWS;
            }
            srow[hidx] = score;  // store sv_{l-1} over consumed emission row
            asm volatile("" ::: "memory");
            const float4 sa = *(const float4*)(srow);
            const float4 sb = *(const float4*)(srow + 4);
            const float s8v = srow[8];
            const float e = erow[j];

            const float cv0 = sa.x + tcol[0];
            const float cv1 = sa.y + tcol[1];
            const float cv2 = sa.z + tcol[2];
            const float cv3 = sa.w + tcol[3];
            const float cv4 = sb.x + tcol[4];
            const float cv5 = sb.y + tcol[5];
            const float cv6 = sb.z + tcol[6];
            const float cv7 = sb.w + tcol[7];
            const float cv8 = s8v + tcol[8];

            const float m0 = fmaxf(cv0, cv1);
            const float m1 = fmaxf(cv2, cv3);
            const float m2 = fmaxf(cv4, cv5);
            const float m3 = fmaxf(cv6, cv7);
            const float best = fmaxf(fmaxf(fmaxf(m0, m1), fmaxf(m2, m3)), cv8);

            score = best + e;
            srow += 12;
            erow += 12;
        }

        // final scores + argmax over states (exchange via row len-1)
        const float fin = (j < Tn) ? score + endT[j] : NEG_INF;
        srow[hidx] = fin;
        asm volatile("" ::: "memory");
        const float4 fa = *(const float4*)(srow);
        const float4 fb = *(const float4*)(srow + 4);
        const float f8v = srow[8];
        const float f0 = fmaxf(fa.x, fa.y);
        const float f1 = fmaxf(fa.z, fa.w);
        const float f2 = fmaxf(fb.x, fb.y);
        const float f3 = fmaxf(fb.z, fb.w);
        const float best_f = fmaxf(fmaxf(fmaxf(f0, f1), fmaxf(f2, f3)), f8v);
        const int g0 = (fa.x == best_f) ? 0 : 9;
        const int g1 = (fa.y == best_f) ? 1 : 9;
        const int g2 = (fa.z == best_f) ? 2 : 9;
        const int g3 = (fa.w == best_f) ? 3 : 9;
        const int g4 = (fb.x == best_f) ? 4 : 9;
        const int g5 = (fb.y == best_f) ? 5 : 9;
        const int g6 = (fb.z == best_f) ? 6 : 9;
        const int g7 = (fb.w == best_f) ? 7 : 9;
        const int g8 = (f8v == best_f) ? 8 : 9;
        const int h0 = min(min(g0, g1), min(g2, g3));
        const int h1 = min(min(g4, g5), min(g6, g7));
        if (lane == 0) {
            s_len = len;
            s_best = best_f;
            s_lasttag = min(min(h0, h1), g8);
        }
    }
    __syncthreads();

    // ================= parallel backpointers (all threads) ===================
    const int len = s_len;
    for (int l = 1 + (int)threadIdx.x; l < len; l += 256) {
        const float* sv = se + (l - 1) * 12;
        const float p0 = sv[0], p1 = sv[1], p2 = sv[2], p3 = sv[3], p4 = sv[4];
        const float p5 = sv[5], p6 = sv[6], p7 = sv[7], p8 = sv[8];
#pragma unroll
        for (int j = 0; j < Tn; j++) {
            const float cv0 = p0 + ttr[0 * Tn + j];
            const float cv1 = p1 + ttr[1 * Tn + j];
            const float cv2 = p2 + ttr[2 * Tn + j];
            const float cv3 = p3 + ttr[3 * Tn + j];
            const float cv4 = p4 + ttr[4 * Tn + j];
            const float cv5 = p5 + ttr[5 * Tn + j];
            const float cv6 = p6 + ttr[6 * Tn + j];
            const float cv7 = p7 + ttr[7 * Tn + j];
            const float cv8 = p8 + ttr[8 * Tn + j];
            const float m0 = fmaxf(cv0, cv1);
            const float m1 = fmaxf(cv2, cv3);
            const float m2 = fmaxf(cv4, cv5);
            const float m3 = fmaxf(cv6, cv7);
            const float best = fmaxf(fmaxf(fmaxf(m0, m1), fmaxf(m2, m3)), cv8);
            const int e0 = (cv0 == best) ? 0 : 9;
            const int e1 = (cv1 == best) ? 1 : 9;
            const int e2 = (cv2 == best) ? 2 : 9;
            const int e3 = (cv3 == best) ? 3 : 9;
            const int e4 = (cv4 == best) ? 4 : 9;
            const int e5 = (cv5 == best) ? 5 : 9;
            const int e6 = (cv6 == best) ? 6 : 9;
            const int e7 = (cv7 == best) ? 7 : 9;
            const int e8 = (cv8 == best) ? 8 : 9;
            const int a0 = min(min(e0, e1), min(e2, e3));
            const int a1 = min(min(e4, e5), min(e6, e7));
            hist8[l * 16 + j] = (uint8_t)min(min(a0, a1), e8);
        }
    }
    // identity maps for l = 0 and l >= len (frozen steps carry same tag)
    for (int l = (int)threadIdx.x; l < Ln; l += 256) {
        if (l == 0 || l >= len) {
#pragma unroll
            for (int j = 0; j < Tn; j++) hist8[l * 16 + j] = (uint8_t)j;
        }
    }
    __syncthreads();

    // ========== parallel backtrace via suffix map composition ================
    // tags[l] = (g_{l+1} o g_{l+2} o ... o g_{1023})(last_tag), g = hist8 rows.
    const int t = (int)threadIdx.x;
    u64 mlo = 0; int mhi = 0;

    // D1: chunk maps C_t = g_{8t} o ... o g_{8t+7} (128 threads)
    if (t < 128) {
        const uint8_t* g7 = hist8 + (8 * t + 7) * 16;
#pragma unroll
        for (int j = 0; j < 8; j++) mlo |= (u64)g7[j] << (8 * j);
        mhi = g7[8];
#pragma unroll
        for (int k = 6; k >= 0; k--) {
            const uint8_t* gk = hist8 + (8 * t + k) * 16;
            u64 nl = 0;
#pragma unroll
            for (int j = 0; j < 8; j++)
                nl |= (u64)gk[(int)((mlo >> (8 * j)) & 0xFF)] << (8 * j);
            const int nh = gk[mhi];
            mlo = nl; mhi = nh;
        }
        *(u64*)(chmap + t * 16) = mlo;
        chmap[t * 16 + 8] = (uint8_t)mhi;
    }
    __syncthreads();

    // D2: Hillis-Steele suffix scan: S_t = C_t o C_{t+1} o ... o C_{127}
    for (int off = 1; off < 128; off <<= 1) {
        u64 nlo = 0; int nhi = 0;
        const bool act = (t < 128) && (t + off < 128);
        if (act) {
            nlo = *(const u64*)(chmap + (t + off) * 16);
            nhi = chmap[(t + off) * 16 + 8];
        }
        __syncthreads();
        if (act) {
            u64 rlo = 0;
#pragma unroll
            for (int j = 0; j < 8; j++) {
                const int idx = (int)((nlo >> (8 * j)) & 0xFF);
                rlo |= (u64)mlook(mlo, mhi, idx) << (8 * j);
            }
            const int rhi = mlook(mlo, mhi, nhi);
            mlo = rlo; mhi = rhi;
            *(u64*)(chmap + t * 16) = mlo;
            chmap[t * 16 + 8] = (uint8_t)mhi;
        }
        __syncthreads();
    }

    // D3: emit tags per chunk (thread t handles l in [8t, 8t+8))
    if (t < 128) {
        int cur;
        if (t == 127) cur = s_lasttag;
        else cur = (int)chmap[(t + 1) * 16 + s_lasttag];  // S_{t+1}(last)
        tags[8 * t + 7] = (uint8_t)cur;
#pragma unroll
        for (int k = 6; k >= 0; k--) {
            cur = (int)hist8[(8 * t + k + 1) * 16 + cur];
            tags[8 * t + k] = (uint8_t)cur;
        }
    }
    __syncthreads();

    // =============================== write out ===============================
    float* ot = out + (size_t)b * Ln;
    for (int k = threadIdx.x; k < Ln; k += 256)
        ot[k] = (k < len) ? (float)tags[k] : 0.f;
    if (threadIdx.x == 0) out[(size_t)Bn * Ln + b] = s_best;
}

// ---------------------------------------------------------------------------
extern "C" void kernel_launch(void* const* d_in, const int* in_sizes, int n_in,
                              void* d_out, int out_size)
{
    const float* x    = (const float*)d_in[0];  // encoder_output [B,L,H2]
    const void*  mask = d_in[1];                // mask [B,L]
    const float* W    = (const float*)d_in[2];  // [T,H2]
    const float* bias = (const float*)d_in[3];  // [T]
    const float* st   = (const float*)d_in[4];  // start_transitions [T]
    const float* en   = (const float*)d_in[5];  // end_transitions [T]
    const float* tr   = (const float*)d_in[6];  // transitions [T,T]
    float* out = (float*)d_out;                 // tags [B*L] then best_score [B]

    cudaFuncSetAttribute(fused_kernel,
                         cudaFuncAttributeMaxDynamicSharedMemorySize, DYN_BYTES);
    fused_kernel<<<Bn, 256, DYN_BYTES>>>(x, mask, W, bias, st, en, tr, out);
}